// round 5
// baseline (speedup 1.0000x reference)
#include <cuda_runtime.h>
#include <cstdint>

#define N_NODES 50000
#define N_EDGES 800000
#define IN_DIM  128
#define H1_DIM  117
#define H2_DIM  42
#define OUT_DIM 24
#define NP1     120   // padded stride for 117-dim buffers (float4-aligned)
#define NP2     44    // padded stride for 42-dim buffers

// ---------------- scratch (device globals; no allocation) ----------------
__device__ int   g_cnt[N_NODES];
__device__ int   g_row[N_NODES + 1];
__device__ int   g_cur[N_NODES];
__device__ int   g_csr[N_EDGES];
__device__ int   g_is64;
__device__ float g_bufA[N_NODES * NP1];
__device__ float g_bufB[N_NODES * NP1];
__device__ float g_bufC[N_NODES * NP1];

// ---------------- CSR build ----------------
__global__ void zero_cnt_kernel() {
    int i = blockIdx.x * blockDim.x + threadIdx.x;
    if (i < N_NODES) g_cnt[i] = 0;
}

// Detect whether edge_index is int64 or int32. If truly int64, the first 1024
// 8-byte words are src indices in [0, N_NODES). If it's int32 data read as
// int64, almost every word combines two indices -> huge values -> fails.
__global__ void detect_kernel(const void* __restrict__ ei) {
    const long long* p = (const long long*)ei;
    int bad = 0;
    for (int i = threadIdx.x; i < 1024; i += blockDim.x) {
        long long v = p[i];
        if (v < 0 || v >= N_NODES) bad = 1;
    }
    int anybad = __syncthreads_or(bad);
    if (threadIdx.x == 0) g_is64 = anybad ? 0 : 1;
}

__global__ void hist_kernel(const void* __restrict__ ei) {
    int e = blockIdx.x * blockDim.x + threadIdx.x;
    if (e >= N_EDGES) return;
    int d = g_is64 ? (int)((const long long*)ei)[N_EDGES + e]
                   : ((const int*)ei)[N_EDGES + e];
    atomicAdd(&g_cnt[d], 1);
}

// Single-block exclusive scan over 50000 counts -> row ptr + cursor copy.
__global__ void scan_kernel() {
    __shared__ int sbuf[1024];
    int tid = threadIdx.x;
    int carry = 0;
    for (int base = 0; base < N_NODES; base += 1024) {
        int i = base + tid;
        int v = (i < N_NODES) ? g_cnt[i] : 0;
        sbuf[tid] = v;
        __syncthreads();
        for (int off = 1; off < 1024; off <<= 1) {
            int t = (tid >= off) ? sbuf[tid - off] : 0;
            __syncthreads();
            sbuf[tid] += t;
            __syncthreads();
        }
        int excl = sbuf[tid] - v + carry;
        if (i < N_NODES) { g_row[i] = excl; g_cur[i] = excl; }
        carry += sbuf[1023];
        __syncthreads();
    }
    if (tid == 0) g_row[N_NODES] = carry;
}

__global__ void fill_kernel(const void* __restrict__ ei) {
    int e = blockIdx.x * blockDim.x + threadIdx.x;
    if (e >= N_EDGES) return;
    int s, d;
    if (g_is64) {
        const long long* p = (const long long*)ei;
        s = (int)p[e]; d = (int)p[N_EDGES + e];
    } else {
        const int* p = (const int*)ei;
        s = p[e]; d = p[N_EDGES + e];
    }
    int pos = atomicAdd(&g_cur[d], 1);
    g_csr[pos] = s;
}

// ---------------- dual GEMM: Y = X@Wl, Z = X@Wr + b ----------------
// Block: 64 nodes x NP padded outputs. Thread tile: 4 nodes x 4 outputs x 2 mats.
template <int NP>
__global__ __launch_bounds__((NP / 4) * 16)
void gemm_dual_kernel(const float* __restrict__ X, int ldx, int K, int NOUT,
                      const float* __restrict__ Wl, const float* __restrict__ Wr,
                      const float* __restrict__ bias,
                      float* __restrict__ Y, float* __restrict__ Z) {
    constexpr int KC = 16, BM = 64, TNG = BM / 4, TOG = NP / 4, NTH = TOG * TNG;
    __shared__ __align__(16) float xs[KC * (BM + 4)];
    __shared__ __align__(16) float wls[KC * NP];
    __shared__ __align__(16) float wrs[KC * NP];

    int tid = threadIdx.x;
    int og = tid / TNG;   // output group (4 outs)
    int ng = tid % TNG;   // node group (4 nodes)
    int nodeBase = blockIdx.x * BM;

    float accY[4][4] = {}, accZ[4][4] = {};

    for (int k0 = 0; k0 < K; k0 += KC) {
        // stage X tile (transposed, padded row to dodge bank conflicts)
        for (int idx = tid; idx < BM * KC; idx += NTH) {
            int n = idx / KC, kk = idx % KC;
            int node = nodeBase + n, k = k0 + kk;
            xs[kk * (BM + 4) + n] =
                (node < N_NODES && k < K) ? X[node * ldx + k] : 0.f;
        }
        // stage weight chunks (pad cols -> 0 so padded outputs are exact 0)
        for (int idx = tid; idx < KC * NP; idx += NTH) {
            int kk = idx / NP, o = idx % NP;
            int k = k0 + kk;
            float vl = 0.f, vr = 0.f;
            if (k < K && o < NOUT) { vl = Wl[k * NOUT + o]; vr = Wr[k * NOUT + o]; }
            wls[kk * NP + o] = vl;
            wrs[kk * NP + o] = vr;
        }
        __syncthreads();
#pragma unroll
        for (int kk = 0; kk < KC; kk++) {
            float4 xv  = *(const float4*)&xs[kk * (BM + 4) + ng * 4];
            float4 wlv = *(const float4*)&wls[kk * NP + og * 4];
            float4 wrv = *(const float4*)&wrs[kk * NP + og * 4];
            float xa[4]  = {xv.x, xv.y, xv.z, xv.w};
            float wla[4] = {wlv.x, wlv.y, wlv.z, wlv.w};
            float wra[4] = {wrv.x, wrv.y, wrv.z, wrv.w};
#pragma unroll
            for (int i = 0; i < 4; i++)
#pragma unroll
                for (int j = 0; j < 4; j++) {
                    accY[i][j] += xa[i] * wla[j];
                    accZ[i][j] += xa[i] * wra[j];
                }
        }
        __syncthreads();
    }

    float b4[4];
#pragma unroll
    for (int j = 0; j < 4; j++) {
        int o = og * 4 + j;
        b4[j] = (o < NOUT) ? bias[o] : 0.f;
    }
#pragma unroll
    for (int i = 0; i < 4; i++) {
        int node = nodeBase + ng * 4 + i;
        if (node < N_NODES) {
            *(float4*)&Y[node * NP + og * 4] =
                make_float4(accY[i][0], accY[i][1], accY[i][2], accY[i][3]);
            *(float4*)&Z[node * NP + og * 4] =
                make_float4(accZ[i][0] + b4[0], accZ[i][1] + b4[1],
                            accZ[i][2] + b4[2], accZ[i][3] + b4[3]);
        }
    }
}

// ---------------- CSR gather: H = [relu](mean_{src in N(n)} Y[src] [+ Z[n]]) --
__global__ void gather_kernel(const float* __restrict__ Y,
                              const float* __restrict__ Z,
                              float* __restrict__ H, int np4, int relu) {
    int idx = blockIdx.x * blockDim.x + threadIdx.x;
    int total = N_NODES * np4;
    if (idx >= total) return;
    int n = idx / np4;
    int f = idx - n * np4;
    int np = np4 * 4;
    int s = g_row[n], e = g_row[n + 1];
    float ax = 0.f, ay = 0.f, az = 0.f, aw = 0.f;
    for (int i = s; i < e; i++) {
        int src = g_csr[i];
        float4 v = *(const float4*)&Y[src * np + f * 4];
        ax += v.x; ay += v.y; az += v.z; aw += v.w;
    }
    int deg = e - s;
    float inv = 1.f / (float)(deg > 1 ? deg : 1);
    ax *= inv; ay *= inv; az *= inv; aw *= inv;
    if (Z) {
        float4 z = *(const float4*)&Z[n * np + f * 4];
        ax += z.x; ay += z.y; az += z.z; aw += z.w;
    }
    if (relu) {
        ax = fmaxf(ax, 0.f); ay = fmaxf(ay, 0.f);
        az = fmaxf(az, 0.f); aw = fmaxf(aw, 0.f);
    }
    *(float4*)&H[n * np + f * 4] = make_float4(ax, ay, az, aw);
}

// ---------------- final layer: mu = A@Wlm + H2@Wrm + bm ; lv analogous ------
__global__ void final_kernel(const float* __restrict__ A,
                             const float* __restrict__ H2,
                             const float* __restrict__ Wlm,
                             const float* __restrict__ Wrm,
                             const float* __restrict__ bm,
                             const float* __restrict__ Wll,
                             const float* __restrict__ Wrl,
                             const float* __restrict__ bl,
                             float* __restrict__ out, int half) {
    __shared__ float s_wlm[H2_DIM * OUT_DIM];
    __shared__ float s_wrm[H2_DIM * OUT_DIM];
    __shared__ float s_wll[H2_DIM * OUT_DIM];
    __shared__ float s_wrl[H2_DIM * OUT_DIM];
    __shared__ float s_b[2 * OUT_DIM];
    int tid = threadIdx.x;
    for (int i = tid; i < H2_DIM * OUT_DIM; i += blockDim.x) {
        s_wlm[i] = Wlm[i]; s_wrm[i] = Wrm[i];
        s_wll[i] = Wll[i]; s_wrl[i] = Wrl[i];
    }
    if (tid < 2 * OUT_DIM) s_b[tid] = (tid < OUT_DIM) ? bm[tid] : bl[tid - OUT_DIM];
    __syncthreads();

    int idx = blockIdx.x * blockDim.x + tid;
    if (idx >= N_NODES * 2 * OUT_DIM) return;
    int n = idx / (2 * OUT_DIM);
    int j = idx - n * (2 * OUT_DIM);
    const float* wl = (j < OUT_DIM) ? s_wlm : s_wll;
    const float* wr = (j < OUT_DIM) ? s_wrm : s_wrl;
    int jj = (j < OUT_DIM) ? j : j - OUT_DIM;
    float acc = s_b[j];
    const float* a = A + n * NP2;
    const float* h = H2 + n * NP2;
#pragma unroll 7
    for (int k = 0; k < H2_DIM; k++)
        acc += a[k] * wl[k * OUT_DIM + jj] + h[k] * wr[k * OUT_DIM + jj];
    out[(j < OUT_DIM ? 0 : half) + n * OUT_DIM + jj] = acc;
}

// ---------------- launch ----------------
extern "C" void kernel_launch(void* const* d_in, const int* in_sizes, int n_in,
                              void* d_out, int out_size) {
    const float* x    = (const float*)d_in[0];
    const void*  ei   = d_in[1];
    const float* Wl1  = (const float*)d_in[2];
    const float* Wr1  = (const float*)d_in[3];
    const float* b1   = (const float*)d_in[4];
    const float* Wl2  = (const float*)d_in[5];
    const float* Wr2  = (const float*)d_in[6];
    const float* b2   = (const float*)d_in[7];
    const float* Wlmu = (const float*)d_in[8];
    const float* Wrmu = (const float*)d_in[9];
    const float* bmu  = (const float*)d_in[10];
    const float* Wllv = (const float*)d_in[11];
    const float* Wrlv = (const float*)d_in[12];
    const float* blv  = (const float*)d_in[13];
    float* out = (float*)d_out;

    float *A, *B, *C;
    cudaGetSymbolAddress((void**)&A, g_bufA);
    cudaGetSymbolAddress((void**)&B, g_bufB);
    cudaGetSymbolAddress((void**)&C, g_bufC);

    // CSR build (reused by all 3 aggregations)
    zero_cnt_kernel<<<(N_NODES + 255) / 256, 256>>>();
    detect_kernel<<<1, 256>>>(ei);
    hist_kernel<<<(N_EDGES + 255) / 256, 256>>>(ei);
    scan_kernel<<<1, 1024>>>();
    fill_kernel<<<(N_EDGES + 255) / 256, 256>>>(ei);

    // Layer 1: transform first (128 -> 117), then aggregate 117-dim
    gemm_dual_kernel<NP1><<<(N_NODES + 63) / 64, (NP1 / 4) * 16>>>(
        x, IN_DIM, IN_DIM, H1_DIM, Wl1, Wr1, b1, A, B);        // A=y1, B=z1
    gather_kernel<<<(N_NODES * (NP1 / 4) + 255) / 256, 256>>>(
        A, B, C, NP1 / 4, 1);                                  // C=h1

    // Layer 2: transform first (117 -> 42), then aggregate 42-dim
    gemm_dual_kernel<NP2><<<(N_NODES + 63) / 64, (NP2 / 4) * 16>>>(
        C, NP1, H1_DIM, H2_DIM, Wl2, Wr2, b2, A, B);           // A=y2, B=z2
    gather_kernel<<<(N_NODES * (NP2 / 4) + 255) / 256, 256>>>(
        A, B, C, NP2 / 4, 1);                                  // C=h2

    // Layer 3: aggregate h2 once (shared by mu and logvar), then tiny GEMM
    gather_kernel<<<(N_NODES * (NP2 / 4) + 255) / 256, 256>>>(
        C, nullptr, A, NP2 / 4, 0);                            // A=mean agg of h2
    final_kernel<<<(N_NODES * 2 * OUT_DIM + 255) / 256, 256>>>(
        A, C, Wlmu, Wrmu, bmu, Wllv, Wrlv, blv, out, out_size / 2);
}

// round 6
// speedup vs baseline: 1.1354x; 1.1354x over previous
#include <cuda_runtime.h>
#include <cstdint>

#define N_NODES 50000
#define N_EDGES 800000
#define IN_DIM  128
#define H1_DIM  117
#define H2_DIM  42
#define OUT_DIM 24
#define NP1     120   // padded stride for 117-dim buffers (float4-aligned)
#define NP2     44    // padded stride for 42-dim buffers

#define SCAN_BLK 1024
#define SCAN_NBLK ((N_NODES + SCAN_BLK - 1) / SCAN_BLK)   // 49

// ---------------- scratch (device globals; no allocation) ----------------
__device__ int   g_cnt[N_NODES];
__device__ int   g_row[N_NODES + 1];
__device__ int   g_cur[N_NODES];
__device__ int   g_csr[N_EDGES];
__device__ int   g_bsum[SCAN_NBLK];
__device__ int   g_is64;
__device__ float g_bufA[N_NODES * NP1];
__device__ float g_bufB[N_NODES * NP1];
__device__ float g_bufC[N_NODES * NP1];

// ---------------- CSR build ----------------
__global__ void zero_cnt_kernel() {
    int i = blockIdx.x * blockDim.x + threadIdx.x;
    if (i < N_NODES) g_cnt[i] = 0;
}

// Detect whether edge_index is int64 or int32. If truly int64, the first 1024
// 8-byte words are src indices in [0, N_NODES). If it's int32 data read as
// int64, almost every word combines two indices -> huge values -> fails.
__global__ void detect_kernel(const void* __restrict__ ei) {
    const long long* p = (const long long*)ei;
    int bad = 0;
    for (int i = threadIdx.x; i < 1024; i += blockDim.x) {
        long long v = p[i];
        if (v < 0 || v >= N_NODES) bad = 1;
    }
    int anybad = __syncthreads_or(bad);
    if (threadIdx.x == 0) g_is64 = anybad ? 0 : 1;
}

__global__ void hist_kernel(const void* __restrict__ ei) {
    int e = blockIdx.x * blockDim.x + threadIdx.x;
    if (e >= N_EDGES) return;
    int d = g_is64 ? (int)((const long long*)ei)[N_EDGES + e]
                   : ((const int*)ei)[N_EDGES + e];
    atomicAdd(&g_cnt[d], 1);
}

// ---- multi-block exclusive scan over g_cnt -> g_row / g_cur ----
// Phase 1: block-local exclusive scan; block sum -> g_bsum.
__global__ void scan1_kernel() {
    __shared__ int sbuf[SCAN_BLK];
    int tid = threadIdx.x;
    int i = blockIdx.x * SCAN_BLK + tid;
    int v = (i < N_NODES) ? g_cnt[i] : 0;
    sbuf[tid] = v;
    __syncthreads();
#pragma unroll
    for (int off = 1; off < SCAN_BLK; off <<= 1) {
        int t = (tid >= off) ? sbuf[tid - off] : 0;
        __syncthreads();
        sbuf[tid] += t;
        __syncthreads();
    }
    if (i < N_NODES) g_row[i] = sbuf[tid] - v;      // local exclusive
    if (tid == SCAN_BLK - 1) g_bsum[blockIdx.x] = sbuf[tid];
}

// Phase 2: tiny scan of the 49 block sums (one warp, serial in smem).
__global__ void scan2_kernel() {
    if (threadIdx.x == 0) {
        int acc = 0;
        for (int b = 0; b < SCAN_NBLK; b++) {
            int v = g_bsum[b];
            g_bsum[b] = acc;       // exclusive
            acc += v;
        }
        g_row[N_NODES] = acc;      // == N_EDGES
    }
}

// Phase 3: add block offsets, init cursors.
__global__ void scan3_kernel() {
    int i = blockIdx.x * SCAN_BLK + threadIdx.x;
    if (i < N_NODES) {
        int r = g_row[i] + g_bsum[blockIdx.x];
        g_row[i] = r;
        g_cur[i] = r;
    }
}

__global__ void fill_kernel(const void* __restrict__ ei) {
    int e = blockIdx.x * blockDim.x + threadIdx.x;
    if (e >= N_EDGES) return;
    int s, d;
    if (g_is64) {
        const long long* p = (const long long*)ei;
        s = (int)p[e]; d = (int)p[N_EDGES + e];
    } else {
        const int* p = (const int*)ei;
        s = p[e]; d = p[N_EDGES + e];
    }
    int pos = atomicAdd(&g_cur[d], 1);
    g_csr[pos] = s;
}

// ---------------- dual GEMM: Y = X@Wl, Z = X@Wr + b ----------------
// Block: 64 nodes x NP padded outputs. Thread tile: 4 nodes x 4 outputs x 2 mats.
template <int NP>
__global__ __launch_bounds__((NP / 4) * 16)
void gemm_dual_kernel(const float* __restrict__ X, int ldx, int K, int NOUT,
                      const float* __restrict__ Wl, const float* __restrict__ Wr,
                      const float* __restrict__ bias,
                      float* __restrict__ Y, float* __restrict__ Z) {
    constexpr int KC = 16, BM = 64, TNG = BM / 4, TOG = NP / 4, NTH = TOG * TNG;
    __shared__ __align__(16) float xs[KC * (BM + 4)];
    __shared__ __align__(16) float wls[KC * NP];
    __shared__ __align__(16) float wrs[KC * NP];

    int tid = threadIdx.x;
    int og = tid / TNG;   // output group (4 outs)
    int ng = tid % TNG;   // node group (4 nodes)
    int nodeBase = blockIdx.x * BM;

    float accY[4][4] = {}, accZ[4][4] = {};

    for (int k0 = 0; k0 < K; k0 += KC) {
        // stage X tile (transposed, padded row to dodge bank conflicts)
        for (int idx = tid; idx < BM * KC; idx += NTH) {
            int n = idx / KC, kk = idx % KC;
            int node = nodeBase + n, k = k0 + kk;
            xs[kk * (BM + 4) + n] =
                (node < N_NODES && k < K) ? X[node * ldx + k] : 0.f;
        }
        // stage weight chunks (pad cols -> 0 so padded outputs are exact 0)
        for (int idx = tid; idx < KC * NP; idx += NTH) {
            int kk = idx / NP, o = idx % NP;
            int k = k0 + kk;
            float vl = 0.f, vr = 0.f;
            if (k < K && o < NOUT) { vl = Wl[k * NOUT + o]; vr = Wr[k * NOUT + o]; }
            wls[kk * NP + o] = vl;
            wrs[kk * NP + o] = vr;
        }
        __syncthreads();
#pragma unroll
        for (int kk = 0; kk < KC; kk++) {
            float4 xv  = *(const float4*)&xs[kk * (BM + 4) + ng * 4];
            float4 wlv = *(const float4*)&wls[kk * NP + og * 4];
            float4 wrv = *(const float4*)&wrs[kk * NP + og * 4];
            float xa[4]  = {xv.x, xv.y, xv.z, xv.w};
            float wla[4] = {wlv.x, wlv.y, wlv.z, wlv.w};
            float wra[4] = {wrv.x, wrv.y, wrv.z, wrv.w};
#pragma unroll
            for (int i = 0; i < 4; i++)
#pragma unroll
                for (int j = 0; j < 4; j++) {
                    accY[i][j] += xa[i] * wla[j];
                    accZ[i][j] += xa[i] * wra[j];
                }
        }
        __syncthreads();
    }

    float b4[4];
#pragma unroll
    for (int j = 0; j < 4; j++) {
        int o = og * 4 + j;
        b4[j] = (o < NOUT) ? bias[o] : 0.f;
    }
#pragma unroll
    for (int i = 0; i < 4; i++) {
        int node = nodeBase + ng * 4 + i;
        if (node < N_NODES) {
            *(float4*)&Y[node * NP + og * 4] =
                make_float4(accY[i][0], accY[i][1], accY[i][2], accY[i][3]);
            *(float4*)&Z[node * NP + og * 4] =
                make_float4(accZ[i][0] + b4[0], accZ[i][1] + b4[1],
                            accZ[i][2] + b4[2], accZ[i][3] + b4[3]);
        }
    }
}

// ---------------- CSR gather: H = [relu](mean_{src in N(n)} Y[src] [+ Z[n]]) --
__global__ void gather_kernel(const float* __restrict__ Y,
                              const float* __restrict__ Z,
                              float* __restrict__ H, int np4, int relu) {
    int idx = blockIdx.x * blockDim.x + threadIdx.x;
    int total = N_NODES * np4;
    if (idx >= total) return;
    int n = idx / np4;
    int f = idx - n * np4;
    int np = np4 * 4;
    int s = g_row[n], e = g_row[n + 1];
    float ax = 0.f, ay = 0.f, az = 0.f, aw = 0.f;
    int i = s;
    for (; i + 1 < e; i += 2) {                 // 2-way ILP on the edge loop
        int s0 = g_csr[i], s1 = g_csr[i + 1];
        float4 v0 = *(const float4*)&Y[s0 * np + f * 4];
        float4 v1 = *(const float4*)&Y[s1 * np + f * 4];
        ax += v0.x + v1.x; ay += v0.y + v1.y;
        az += v0.z + v1.z; aw += v0.w + v1.w;
    }
    if (i < e) {
        int s0 = g_csr[i];
        float4 v0 = *(const float4*)&Y[s0 * np + f * 4];
        ax += v0.x; ay += v0.y; az += v0.z; aw += v0.w;
    }
    int deg = e - s;
    float inv = 1.f / (float)(deg > 1 ? deg : 1);
    ax *= inv; ay *= inv; az *= inv; aw *= inv;
    if (Z) {
        float4 z = *(const float4*)&Z[n * np + f * 4];
        ax += z.x; ay += z.y; az += z.z; aw += z.w;
    }
    if (relu) {
        ax = fmaxf(ax, 0.f); ay = fmaxf(ay, 0.f);
        az = fmaxf(az, 0.f); aw = fmaxf(aw, 0.f);
    }
    *(float4*)&H[n * np + f * 4] = make_float4(ax, ay, az, aw);
}

// ---------------- final layer: mu = A@Wlm + H2@Wrm + bm ; lv analogous ------
__global__ void final_kernel(const float* __restrict__ A,
                             const float* __restrict__ H2,
                             const float* __restrict__ Wlm,
                             const float* __restrict__ Wrm,
                             const float* __restrict__ bm,
                             const float* __restrict__ Wll,
                             const float* __restrict__ Wrl,
                             const float* __restrict__ bl,
                             float* __restrict__ out, int half) {
    __shared__ float s_wlm[H2_DIM * OUT_DIM];
    __shared__ float s_wrm[H2_DIM * OUT_DIM];
    __shared__ float s_wll[H2_DIM * OUT_DIM];
    __shared__ float s_wrl[H2_DIM * OUT_DIM];
    __shared__ float s_b[2 * OUT_DIM];
    int tid = threadIdx.x;
    for (int i = tid; i < H2_DIM * OUT_DIM; i += blockDim.x) {
        s_wlm[i] = Wlm[i]; s_wrm[i] = Wrm[i];
        s_wll[i] = Wll[i]; s_wrl[i] = Wrl[i];
    }
    if (tid < 2 * OUT_DIM) s_b[tid] = (tid < OUT_DIM) ? bm[tid] : bl[tid - OUT_DIM];
    __syncthreads();

    int idx = blockIdx.x * blockDim.x + tid;
    if (idx >= N_NODES * 2 * OUT_DIM) return;
    int n = idx / (2 * OUT_DIM);
    int j = idx - n * (2 * OUT_DIM);
    const float* wl = (j < OUT_DIM) ? s_wlm : s_wll;
    const float* wr = (j < OUT_DIM) ? s_wrm : s_wrl;
    int jj = (j < OUT_DIM) ? j : j - OUT_DIM;
    float acc = s_b[j];
    const float* a = A + n * NP2;
    const float* h = H2 + n * NP2;
#pragma unroll 7
    for (int k = 0; k < H2_DIM; k++)
        acc += a[k] * wl[k * OUT_DIM + jj] + h[k] * wr[k * OUT_DIM + jj];
    out[(j < OUT_DIM ? 0 : half) + n * OUT_DIM + jj] = acc;
}

// ---------------- launch ----------------
extern "C" void kernel_launch(void* const* d_in, const int* in_sizes, int n_in,
                              void* d_out, int out_size) {
    const float* x    = (const float*)d_in[0];
    const void*  ei   = d_in[1];
    const float* Wl1  = (const float*)d_in[2];
    const float* Wr1  = (const float*)d_in[3];
    const float* b1   = (const float*)d_in[4];
    const float* Wl2  = (const float*)d_in[5];
    const float* Wr2  = (const float*)d_in[6];
    const float* b2   = (const float*)d_in[7];
    const float* Wlmu = (const float*)d_in[8];
    const float* Wrmu = (const float*)d_in[9];
    const float* bmu  = (const float*)d_in[10];
    const float* Wllv = (const float*)d_in[11];
    const float* Wrlv = (const float*)d_in[12];
    const float* blv  = (const float*)d_in[13];
    float* out = (float*)d_out;

    float *A, *B, *C;
    cudaGetSymbolAddress((void**)&A, g_bufA);
    cudaGetSymbolAddress((void**)&B, g_bufB);
    cudaGetSymbolAddress((void**)&C, g_bufC);

    // CSR build (reused by all 3 aggregations)
    zero_cnt_kernel<<<(N_NODES + 255) / 256, 256>>>();
    detect_kernel<<<1, 256>>>(ei);
    hist_kernel<<<(N_EDGES + 255) / 256, 256>>>(ei);
    scan1_kernel<<<SCAN_NBLK, SCAN_BLK>>>();
    scan2_kernel<<<1, 32>>>();
    scan3_kernel<<<SCAN_NBLK, SCAN_BLK>>>();
    fill_kernel<<<(N_EDGES + 255) / 256, 256>>>(ei);

    // Layer 1: transform first (128 -> 117), then aggregate 117-dim
    gemm_dual_kernel<NP1><<<(N_NODES + 63) / 64, (NP1 / 4) * 16>>>(
        x, IN_DIM, IN_DIM, H1_DIM, Wl1, Wr1, b1, A, B);        // A=y1, B=z1
    gather_kernel<<<(N_NODES * (NP1 / 4) + 255) / 256, 256>>>(
        A, B, C, NP1 / 4, 1);                                  // C=h1

    // Layer 2: transform first (117 -> 42), then aggregate 42-dim
    gemm_dual_kernel<NP2><<<(N_NODES + 63) / 64, (NP2 / 4) * 16>>>(
        C, NP1, H1_DIM, H2_DIM, Wl2, Wr2, b2, A, B);           // A=y2, B=z2
    gather_kernel<<<(N_NODES * (NP2 / 4) + 255) / 256, 256>>>(
        A, B, C, NP2 / 4, 1);                                  // C=h2

    // Layer 3: aggregate h2 once (shared by mu and logvar), then tiny GEMM
    gather_kernel<<<(N_NODES * (NP2 / 4) + 255) / 256, 256>>>(
        C, nullptr, A, NP2 / 4, 0);                            // A=mean agg of h2
    final_kernel<<<(N_NODES * 2 * OUT_DIM + 255) / 256, 256>>>(
        A, C, Wlmu, Wrmu, bmu, Wllv, Wrlv, blv, out, out_size / 2);
}

// round 7
// speedup vs baseline: 1.3613x; 1.1989x over previous
#include <cuda_runtime.h>
#include <cstdint>

#define N_NODES 50000
#define N_EDGES 800000
#define IN_DIM  128
#define H1_DIM  117
#define H2_DIM  42
#define OUT_DIM 24
#define NP1     120   // padded stride for 117-dim buffers (float4-aligned)
#define NP2     44    // padded stride for 42-dim buffers

#define SCAN_BLK 1024
#define SCAN_NBLK ((N_NODES + SCAN_BLK - 1) / SCAN_BLK)   // 49

typedef unsigned long long ull;

// ---------------- packed fp32x2 helpers (sm_100+; full fp32 precision) ------
__device__ __forceinline__ void ffma2(ull& acc, ull a, ull b) {
    asm("fma.rn.f32x2 %0, %1, %2, %0;" : "+l"(acc) : "l"(a), "l"(b));
}
__device__ __forceinline__ ull fpack2(float lo, float hi) {
    ull r; asm("mov.b64 %0, {%1, %2};" : "=l"(r) : "f"(lo), "f"(hi)); return r;
}
__device__ __forceinline__ float2 funpack2(ull v) {
    float2 r; asm("mov.b64 {%0, %1}, %2;" : "=f"(r.x), "=f"(r.y) : "l"(v)); return r;
}

// ---------------- scratch (device globals; no allocation) ----------------
__device__ int   g_cnt[N_NODES];
__device__ int   g_row[N_NODES + 1];
__device__ int   g_cur[N_NODES];
__device__ int   g_csr[N_EDGES];
__device__ int   g_bsum[SCAN_NBLK];
__device__ int   g_is64;
__device__ float g_bufA[N_NODES * NP1];
__device__ float g_bufB[N_NODES * NP1];
__device__ float g_bufC[N_NODES * NP1];

// ---------------- CSR build ----------------
// Zero counts; block 0 additionally detects int64 vs int32 edge_index.
__global__ void init_kernel(const void* __restrict__ ei) {
    int i = blockIdx.x * blockDim.x + threadIdx.x;
    if (i < N_NODES) g_cnt[i] = 0;
    if (blockIdx.x == 0) {
        const long long* p = (const long long*)ei;
        int bad = 0;
        for (int t = threadIdx.x; t < 1024; t += blockDim.x) {
            long long v = p[t];
            if (v < 0 || v >= N_NODES) bad = 1;
        }
        int anybad = __syncthreads_or(bad);
        if (threadIdx.x == 0) g_is64 = anybad ? 0 : 1;
    }
}

__global__ void hist_kernel(const void* __restrict__ ei) {
    int e = blockIdx.x * blockDim.x + threadIdx.x;
    if (e >= N_EDGES) return;
    int d = g_is64 ? (int)((const long long*)ei)[N_EDGES + e]
                   : ((const int*)ei)[N_EDGES + e];
    atomicAdd(&g_cnt[d], 1);
}

// Phase 1: block-local exclusive scan; block sum -> g_bsum.
__global__ void scan1_kernel() {
    __shared__ int sbuf[SCAN_BLK];
    int tid = threadIdx.x;
    int i = blockIdx.x * SCAN_BLK + tid;
    int v = (i < N_NODES) ? g_cnt[i] : 0;
    sbuf[tid] = v;
    __syncthreads();
#pragma unroll
    for (int off = 1; off < SCAN_BLK; off <<= 1) {
        int t = (tid >= off) ? sbuf[tid - off] : 0;
        __syncthreads();
        sbuf[tid] += t;
        __syncthreads();
    }
    if (i < N_NODES) g_row[i] = sbuf[tid] - v;      // local exclusive
    if (tid == SCAN_BLK - 1) g_bsum[blockIdx.x] = sbuf[tid];
}

// Phase 2: parallel scan of the 49 block sums (one 64-thread block).
__global__ void scan2_kernel() {
    __shared__ int s[64];
    int t = threadIdx.x;
    int v = (t < SCAN_NBLK) ? g_bsum[t] : 0;
    s[t] = v;
    __syncthreads();
#pragma unroll
    for (int off = 1; off < 64; off <<= 1) {
        int u = (t >= off) ? s[t - off] : 0;
        __syncthreads();
        s[t] += u;
        __syncthreads();
    }
    if (t < SCAN_NBLK) g_bsum[t] = s[t] - v;        // exclusive
    if (t == SCAN_NBLK - 1) g_row[N_NODES] = s[t];  // == N_EDGES
}

// Phase 3: add block offsets, init cursors.
__global__ void scan3_kernel() {
    int i = blockIdx.x * SCAN_BLK + threadIdx.x;
    if (i < N_NODES) {
        int r = g_row[i] + g_bsum[blockIdx.x];
        g_row[i] = r;
        g_cur[i] = r;
    }
}

__global__ void fill_kernel(const void* __restrict__ ei) {
    int e = blockIdx.x * blockDim.x + threadIdx.x;
    if (e >= N_EDGES) return;
    int s, d;
    if (g_is64) {
        const long long* p = (const long long*)ei;
        s = (int)p[e]; d = (int)p[N_EDGES + e];
    } else {
        const int* p = (const int*)ei;
        s = p[e]; d = p[N_EDGES + e];
    }
    int pos = atomicAdd(&g_cur[d], 1);
    g_csr[pos] = s;
}

// ---------------- dual GEMM: Y = X@Wl, Z = X@Wr + b (packed f32x2) ---------
// Block: 64 nodes x NP outputs. Thread: 4 nodes x 4 outputs (2 pairs) x 2 mats.
template <int NP>
__global__ __launch_bounds__((NP / 4) * 16)
void gemm_dual_kernel(const float* __restrict__ X, int ldx, int K, int NOUT,
                      const float* __restrict__ Wl, const float* __restrict__ Wr,
                      const float* __restrict__ bias,
                      float* __restrict__ Y, float* __restrict__ Z) {
    constexpr int KC = 32, BM = 64, TNG = BM / 4, TOG = NP / 4, NTH = TOG * TNG;
    constexpr int XST = BM + 4;                       // xs row stride (17*16B)
    __shared__ __align__(16) float xs[KC * XST];
    __shared__ __align__(16) float wls[KC * NP];
    __shared__ __align__(16) float wrs[KC * NP];

    int tid = threadIdx.x;
    int og = tid / TNG;   // output group (4 outs = 2 pairs)
    int ng = tid % TNG;   // node group (4 nodes)
    int nodeBase = blockIdx.x * BM;

    ull accY[4][2] = {}, accZ[4][2] = {};             // 0 bits == {0.f,0.f}

    for (int k0 = 0; k0 < K; k0 += KC) {
        // stage X tile (warp = one node row x 32 k -> coalesced global reads)
        for (int idx = tid; idx < BM * KC; idx += NTH) {
            int n = idx / KC, kk = idx % KC;
            int node = nodeBase + n, k = k0 + kk;
            xs[kk * XST + n] =
                (node < N_NODES && k < K) ? X[node * ldx + k] : 0.f;
        }
        // stage weight chunks (pad cols -> 0 so padded outputs are exact 0)
        for (int idx = tid; idx < KC * NP; idx += NTH) {
            int kk = idx / NP, o = idx % NP;
            int k = k0 + kk;
            float vl = 0.f, vr = 0.f;
            if (k < K && o < NOUT) { vl = Wl[k * NOUT + o]; vr = Wr[k * NOUT + o]; }
            wls[kk * NP + o] = vl;
            wrs[kk * NP + o] = vr;
        }
        __syncthreads();
#pragma unroll
        for (int kk = 0; kk < KC; kk++) {
            float4 xv = *(const float4*)&xs[kk * XST + ng * 4];
            const float* wlp = &wls[kk * NP + og * 4];
            const float* wrp = &wrs[kk * NP + og * 4];
            ull wl0 = *(const ull*)(wlp),     wl1 = *(const ull*)(wlp + 2);
            ull wr0 = *(const ull*)(wrp),     wr1 = *(const ull*)(wrp + 2);
            ull x0 = fpack2(xv.x, xv.x), x1 = fpack2(xv.y, xv.y);
            ull x2 = fpack2(xv.z, xv.z), x3 = fpack2(xv.w, xv.w);
            ffma2(accY[0][0], x0, wl0); ffma2(accY[0][1], x0, wl1);
            ffma2(accY[1][0], x1, wl0); ffma2(accY[1][1], x1, wl1);
            ffma2(accY[2][0], x2, wl0); ffma2(accY[2][1], x2, wl1);
            ffma2(accY[3][0], x3, wl0); ffma2(accY[3][1], x3, wl1);
            ffma2(accZ[0][0], x0, wr0); ffma2(accZ[0][1], x0, wr1);
            ffma2(accZ[1][0], x1, wr0); ffma2(accZ[1][1], x1, wr1);
            ffma2(accZ[2][0], x2, wr0); ffma2(accZ[2][1], x2, wr1);
            ffma2(accZ[3][0], x3, wr0); ffma2(accZ[3][1], x3, wr1);
        }
        __syncthreads();
    }

    float b4[4];
#pragma unroll
    for (int j = 0; j < 4; j++) {
        int o = og * 4 + j;
        b4[j] = (o < NOUT) ? bias[o] : 0.f;
    }
#pragma unroll
    for (int i = 0; i < 4; i++) {
        int node = nodeBase + ng * 4 + i;
        if (node < N_NODES) {
            float2 y0 = funpack2(accY[i][0]), y1 = funpack2(accY[i][1]);
            float2 z0 = funpack2(accZ[i][0]), z1 = funpack2(accZ[i][1]);
            *(float4*)&Y[node * NP + og * 4] = make_float4(y0.x, y0.y, y1.x, y1.y);
            *(float4*)&Z[node * NP + og * 4] =
                make_float4(z0.x + b4[0], z0.y + b4[1], z1.x + b4[2], z1.y + b4[3]);
        }
    }
}

// ---------------- CSR gather: H = [relu](mean_{src in N(n)} Y[src] [+ Z[n]]) --
template <int NP4, int RELU, int HAS_Z>
__global__ void gather_kernel(const float* __restrict__ Y,
                              const float* __restrict__ Z,
                              float* __restrict__ H) {
    int idx = blockIdx.x * blockDim.x + threadIdx.x;
    if (idx >= N_NODES * NP4) return;
    int n = idx / NP4;
    int f = idx - n * NP4;
    constexpr int np = NP4 * 4;
    int s = g_row[n], e = g_row[n + 1];
    float ax = 0.f, ay = 0.f, az = 0.f, aw = 0.f;
    int i = s;
    for (; i + 3 < e; i += 4) {                 // 4-way MLP on the edge loop
        int s0 = g_csr[i], s1 = g_csr[i + 1], s2 = g_csr[i + 2], s3 = g_csr[i + 3];
        float4 v0 = *(const float4*)&Y[s0 * np + f * 4];
        float4 v1 = *(const float4*)&Y[s1 * np + f * 4];
        float4 v2 = *(const float4*)&Y[s2 * np + f * 4];
        float4 v3 = *(const float4*)&Y[s3 * np + f * 4];
        ax += (v0.x + v1.x) + (v2.x + v3.x);
        ay += (v0.y + v1.y) + (v2.y + v3.y);
        az += (v0.z + v1.z) + (v2.z + v3.z);
        aw += (v0.w + v1.w) + (v2.w + v3.w);
    }
    for (; i < e; i++) {
        int s0 = g_csr[i];
        float4 v0 = *(const float4*)&Y[s0 * np + f * 4];
        ax += v0.x; ay += v0.y; az += v0.z; aw += v0.w;
    }
    int deg = e - s;
    float inv = 1.f / (float)(deg > 1 ? deg : 1);
    ax *= inv; ay *= inv; az *= inv; aw *= inv;
    if (HAS_Z) {
        float4 z = *(const float4*)&Z[n * np + f * 4];
        ax += z.x; ay += z.y; az += z.z; aw += z.w;
    }
    if (RELU) {
        ax = fmaxf(ax, 0.f); ay = fmaxf(ay, 0.f);
        az = fmaxf(az, 0.f); aw = fmaxf(aw, 0.f);
    }
    *(float4*)&H[n * np + f * 4] = make_float4(ax, ay, az, aw);
}

// ---------------- final layer: mu = A@Wlm + H2@Wrm + bm ; lv analogous ------
// Weights transposed in smem -> both f32x2 operands are direct 64-bit loads.
__global__ void final_kernel(const float* __restrict__ A,
                             const float* __restrict__ H2,
                             const float* __restrict__ Wlm,
                             const float* __restrict__ Wrm,
                             const float* __restrict__ bm,
                             const float* __restrict__ Wll,
                             const float* __restrict__ Wrl,
                             const float* __restrict__ bl,
                             float* __restrict__ out, int half) {
    __shared__ __align__(8) float s_wlm[OUT_DIM * H2_DIM];  // [j][k]
    __shared__ __align__(8) float s_wrm[OUT_DIM * H2_DIM];
    __shared__ __align__(8) float s_wll[OUT_DIM * H2_DIM];
    __shared__ __align__(8) float s_wrl[OUT_DIM * H2_DIM];
    __shared__ float s_b[2 * OUT_DIM];
    int tid = threadIdx.x;
    for (int i = tid; i < H2_DIM * OUT_DIM; i += blockDim.x) {
        int k = i / OUT_DIM, j = i - k * OUT_DIM;
        s_wlm[j * H2_DIM + k] = Wlm[i]; s_wrm[j * H2_DIM + k] = Wrm[i];
        s_wll[j * H2_DIM + k] = Wll[i]; s_wrl[j * H2_DIM + k] = Wrl[i];
    }
    if (tid < 2 * OUT_DIM) s_b[tid] = (tid < OUT_DIM) ? bm[tid] : bl[tid - OUT_DIM];
    __syncthreads();

    int idx = blockIdx.x * blockDim.x + tid;
    if (idx >= N_NODES * 2 * OUT_DIM) return;
    int n = idx / (2 * OUT_DIM);
    int j = idx - n * (2 * OUT_DIM);
    const float* wl = (j < OUT_DIM) ? s_wlm : s_wll;
    const float* wr = (j < OUT_DIM) ? s_wrm : s_wrl;
    int jj = (j < OUT_DIM) ? j : j - OUT_DIM;
    const float* a = A + n * NP2;
    const float* h = H2 + n * NP2;
    const float* wlr = wl + jj * H2_DIM;
    const float* wrr = wr + jj * H2_DIM;
    ull accA = 0ULL, accB = 0ULL;
#pragma unroll
    for (int kp = 0; kp < H2_DIM / 2; kp++) {
        ffma2(accA, *(const ull*)(a + 2 * kp), *(const ull*)(wlr + 2 * kp));
        ffma2(accB, *(const ull*)(h + 2 * kp), *(const ull*)(wrr + 2 * kp));
    }
    float2 ra = funpack2(accA), rb = funpack2(accB);
    float acc = s_b[j] + (ra.x + ra.y) + (rb.x + rb.y);
    out[(j < OUT_DIM ? 0 : half) + n * OUT_DIM + jj] = acc;
}

// ---------------- launch ----------------
extern "C" void kernel_launch(void* const* d_in, const int* in_sizes, int n_in,
                              void* d_out, int out_size) {
    const float* x    = (const float*)d_in[0];
    const void*  ei   = d_in[1];
    const float* Wl1  = (const float*)d_in[2];
    const float* Wr1  = (const float*)d_in[3];
    const float* b1   = (const float*)d_in[4];
    const float* Wl2  = (const float*)d_in[5];
    const float* Wr2  = (const float*)d_in[6];
    const float* b2   = (const float*)d_in[7];
    const float* Wlmu = (const float*)d_in[8];
    const float* Wrmu = (const float*)d_in[9];
    const float* bmu  = (const float*)d_in[10];
    const float* Wllv = (const float*)d_in[11];
    const float* Wrlv = (const float*)d_in[12];
    const float* blv  = (const float*)d_in[13];
    float* out = (float*)d_out;

    float *A, *B, *C;
    cudaGetSymbolAddress((void**)&A, g_bufA);
    cudaGetSymbolAddress((void**)&B, g_bufB);
    cudaGetSymbolAddress((void**)&C, g_bufC);

    // CSR build (gemm1 is independent of CSR; fill may run after it)
    init_kernel<<<SCAN_NBLK, SCAN_BLK>>>(ei);                         // #0
    hist_kernel<<<(N_EDGES + 255) / 256, 256>>>(ei);                  // #1
    scan1_kernel<<<SCAN_NBLK, SCAN_BLK>>>();                          // #2
    scan2_kernel<<<1, 64>>>();                                        // #3
    scan3_kernel<<<SCAN_NBLK, SCAN_BLK>>>();                          // #4

    // Layer 1 transform (128 -> 117); placed at launch index 5 for ncu -s 5
    gemm_dual_kernel<NP1><<<(N_NODES + 63) / 64, (NP1 / 4) * 16>>>(
        x, IN_DIM, IN_DIM, H1_DIM, Wl1, Wr1, b1, A, B);               // #5

    fill_kernel<<<(N_EDGES + 255) / 256, 256>>>(ei);                  // #6

    // Layer 1 aggregate (117-dim)
    gather_kernel<NP1 / 4, 1, 1><<<(N_NODES * (NP1 / 4) + 255) / 256, 256>>>(
        A, B, C);                                                     // C=h1

    // Layer 2: transform first (117 -> 42), then aggregate 42-dim
    gemm_dual_kernel<NP2><<<(N_NODES + 63) / 64, (NP2 / 4) * 16>>>(
        C, NP1, H1_DIM, H2_DIM, Wl2, Wr2, b2, A, B);
    gather_kernel<NP2 / 4, 1, 1><<<(N_NODES * (NP2 / 4) + 255) / 256, 256>>>(
        A, B, C);                                                     // C=h2

    // Layer 3: aggregate h2 once (shared by mu and logvar), then tiny GEMM
    gather_kernel<NP2 / 4, 0, 0><<<(N_NODES * (NP2 / 4) + 255) / 256, 256>>>(
        C, nullptr, A);
    final_kernel<<<(N_NODES * 2 * OUT_DIM + 255) / 256, 256>>>(
        A, C, Wlmu, Wrmu, bmu, Wllv, Wrlv, blv, out, out_size / 2);
}

// round 9
// speedup vs baseline: 1.4535x; 1.0677x over previous
#include <cuda_runtime.h>
#include <cstdint>

#define N_NODES 50000
#define N_EDGES 800000
#define IN_DIM  128
#define H1_DIM  117
#define H2_DIM  42
#define OUT_DIM 24
#define NP1     120   // padded stride for 117-dim buffers (float4-aligned)
#define NP2     44    // padded stride for 42-dim buffers

#define SCAN_BLK 1024
#define SCAN_NBLK ((N_NODES + SCAN_BLK - 1) / SCAN_BLK)   // 49

typedef unsigned long long ull;

// ---------------- packed fp32x2 helpers (sm_100+; full fp32 precision) ------
__device__ __forceinline__ void ffma2(ull& acc, ull a, ull b) {
    asm("fma.rn.f32x2 %0, %1, %2, %0;" : "+l"(acc) : "l"(a), "l"(b));
}
__device__ __forceinline__ ull fpack2(float lo, float hi) {
    ull r; asm("mov.b64 %0, {%1, %2};" : "=l"(r) : "f"(lo), "f"(hi)); return r;
}
__device__ __forceinline__ float2 funpack2(ull v) {
    float2 r; asm("mov.b64 {%0, %1}, %2;" : "=f"(r.x), "=f"(r.y) : "l"(v)); return r;
}

// ---------------- scratch (device globals; no allocation) ----------------
__device__ int   g_cnt[N_NODES];
__device__ int   g_row[N_NODES + 1];
__device__ int   g_cur[N_NODES];
__device__ int   g_csr[N_EDGES];
__device__ int   g_bsum[SCAN_NBLK];
__device__ int   g_is64;
__device__ float g_bufA[N_NODES * NP1];
__device__ float g_bufB[N_NODES * NP1];
__device__ float g_bufC[N_NODES * NP1];

// ---------------- CSR build ----------------
// Zero counts; block 0 additionally detects int64 vs int32 edge_index.
__global__ void init_kernel(const void* __restrict__ ei) {
    int i = blockIdx.x * blockDim.x + threadIdx.x;
    if (i < N_NODES) g_cnt[i] = 0;
    if (blockIdx.x == 0) {
        const long long* p = (const long long*)ei;
        int bad = 0;
        for (int t = threadIdx.x; t < 1024; t += blockDim.x) {
            long long v = p[t];
            if (v < 0 || v >= N_NODES) bad = 1;
        }
        int anybad = __syncthreads_or(bad);
        if (threadIdx.x == 0) g_is64 = anybad ? 0 : 1;
    }
}

// 2 edges per thread, vectorized dst loads.
__global__ void hist_kernel(const void* __restrict__ ei) {
    int t = blockIdx.x * blockDim.x + threadIdx.x;
    if (t >= N_EDGES / 2) return;
    int d0, d1;
    if (g_is64) {
        const longlong2* p = (const longlong2*)((const long long*)ei + N_EDGES);
        longlong2 v = p[t];
        d0 = (int)v.x; d1 = (int)v.y;
    } else {
        const int2* p = (const int2*)((const int*)ei + N_EDGES);
        int2 v = p[t];
        d0 = v.x; d1 = v.y;
    }
    atomicAdd(&g_cnt[d0], 1);
    atomicAdd(&g_cnt[d1], 1);
}

// Phase 1: block-local exclusive scan; block sum -> g_bsum.
__global__ void scan1_kernel() {
    __shared__ int sbuf[SCAN_BLK];
    int tid = threadIdx.x;
    int i = blockIdx.x * SCAN_BLK + tid;
    int v = (i < N_NODES) ? g_cnt[i] : 0;
    sbuf[tid] = v;
    __syncthreads();
#pragma unroll
    for (int off = 1; off < SCAN_BLK; off <<= 1) {
        int t = (tid >= off) ? sbuf[tid - off] : 0;
        __syncthreads();
        sbuf[tid] += t;
        __syncthreads();
    }
    if (i < N_NODES) g_row[i] = sbuf[tid] - v;      // local exclusive
    if (tid == SCAN_BLK - 1) g_bsum[blockIdx.x] = sbuf[tid];
}

// Phase 2: parallel scan of the 49 block sums (one 64-thread block).
__global__ void scan2_kernel() {
    __shared__ int s[64];
    int t = threadIdx.x;
    int v = (t < SCAN_NBLK) ? g_bsum[t] : 0;
    s[t] = v;
    __syncthreads();
#pragma unroll
    for (int off = 1; off < 64; off <<= 1) {
        int u = (t >= off) ? s[t - off] : 0;
        __syncthreads();
        s[t] += u;
        __syncthreads();
    }
    if (t < SCAN_NBLK) g_bsum[t] = s[t] - v;        // exclusive
    if (t == SCAN_NBLK - 1) g_row[N_NODES] = s[t];  // == N_EDGES
}

// Phase 3: add block offsets, init cursors.
__global__ void scan3_kernel() {
    int i = blockIdx.x * SCAN_BLK + threadIdx.x;
    if (i < N_NODES) {
        int r = g_row[i] + g_bsum[blockIdx.x];
        g_row[i] = r;
        g_cur[i] = r;
    }
}

// 2 edges per thread, vectorized src/dst loads.
__global__ void fill_kernel(const void* __restrict__ ei) {
    int t = blockIdx.x * blockDim.x + threadIdx.x;
    if (t >= N_EDGES / 2) return;
    int s0, s1, d0, d1;
    if (g_is64) {
        const longlong2* ps = (const longlong2*)ei;
        const longlong2* pd = (const longlong2*)((const long long*)ei + N_EDGES);
        longlong2 vs = ps[t], vd = pd[t];
        s0 = (int)vs.x; s1 = (int)vs.y; d0 = (int)vd.x; d1 = (int)vd.y;
    } else {
        const int2* ps = (const int2*)ei;
        const int2* pd = (const int2*)((const int*)ei + N_EDGES);
        int2 vs = ps[t], vd = pd[t];
        s0 = vs.x; s1 = vs.y; d0 = vd.x; d1 = vd.y;
    }
    int p0 = atomicAdd(&g_cur[d0], 1);
    g_csr[p0] = s0;
    int p1 = atomicAdd(&g_cur[d1], 1);
    g_csr[p1] = s1;
}

// ---------------- dual GEMM: Y = X@Wl, Z = X@Wr + b (packed f32x2) ---------
// Block: 64 nodes x NP outputs. Thread: 4 nodes x 4 outputs (2 pairs) x 2 mats.
template <int NP>
__global__ __launch_bounds__((NP / 4) * 16)
void gemm_dual_kernel(const float* __restrict__ X, int ldx, int K, int NOUT,
                      const float* __restrict__ Wl, const float* __restrict__ Wr,
                      const float* __restrict__ bias,
                      float* __restrict__ Y, float* __restrict__ Z) {
    constexpr int KC = 32, BM = 64, TNG = BM / 4, TOG = NP / 4, NTH = TOG * TNG;
    constexpr int XST = BM + 4;                       // xs row stride (17*16B)
    __shared__ __align__(16) float xs[KC * XST];
    __shared__ __align__(16) float wls[KC * NP];
    __shared__ __align__(16) float wrs[KC * NP];

    int tid = threadIdx.x;
    int og = tid / TNG;   // output group (4 outs = 2 pairs)
    int ng = tid % TNG;   // node group (4 nodes)
    int nodeBase = blockIdx.x * BM;

    ull accY[4][2] = {}, accZ[4][2] = {};             // 0 bits == {0.f,0.f}

    for (int k0 = 0; k0 < K; k0 += KC) {
        // stage X tile (warp = one node row x 32 k -> coalesced global reads)
        for (int idx = tid; idx < BM * KC; idx += NTH) {
            int n = idx / KC, kk = idx % KC;
            int node = nodeBase + n, k = k0 + kk;
            xs[kk * XST + n] =
                (node < N_NODES && k < K) ? X[node * ldx + k] : 0.f;
        }
        // stage weight chunks (pad cols -> 0 so padded outputs are exact 0)
        for (int idx = tid; idx < KC * NP; idx += NTH) {
            int kk = idx / NP, o = idx % NP;
            int k = k0 + kk;
            float vl = 0.f, vr = 0.f;
            if (k < K && o < NOUT) { vl = Wl[k * NOUT + o]; vr = Wr[k * NOUT + o]; }
            wls[kk * NP + o] = vl;
            wrs[kk * NP + o] = vr;
        }
        __syncthreads();
#pragma unroll
        for (int kk = 0; kk < KC; kk++) {
            float4 xv = *(const float4*)&xs[kk * XST + ng * 4];
            const float* wlp = &wls[kk * NP + og * 4];
            const float* wrp = &wrs[kk * NP + og * 4];
            ull wl0 = *(const ull*)(wlp),     wl1 = *(const ull*)(wlp + 2);
            ull wr0 = *(const ull*)(wrp),     wr1 = *(const ull*)(wrp + 2);
            ull x0 = fpack2(xv.x, xv.x), x1 = fpack2(xv.y, xv.y);
            ull x2 = fpack2(xv.z, xv.z), x3 = fpack2(xv.w, xv.w);
            ffma2(accY[0][0], x0, wl0); ffma2(accY[0][1], x0, wl1);
            ffma2(accY[1][0], x1, wl0); ffma2(accY[1][1], x1, wl1);
            ffma2(accY[2][0], x2, wl0); ffma2(accY[2][1], x2, wl1);
            ffma2(accY[3][0], x3, wl0); ffma2(accY[3][1], x3, wl1);
            ffma2(accZ[0][0], x0, wr0); ffma2(accZ[0][1], x0, wr1);
            ffma2(accZ[1][0], x1, wr0); ffma2(accZ[1][1], x1, wr1);
            ffma2(accZ[2][0], x2, wr0); ffma2(accZ[2][1], x2, wr1);
            ffma2(accZ[3][0], x3, wr0); ffma2(accZ[3][1], x3, wr1);
        }
        __syncthreads();
    }

    float b4[4];
#pragma unroll
    for (int j = 0; j < 4; j++) {
        int o = og * 4 + j;
        b4[j] = (o < NOUT) ? bias[o] : 0.f;
    }
#pragma unroll
    for (int i = 0; i < 4; i++) {
        int node = nodeBase + ng * 4 + i;
        if (node < N_NODES) {
            float2 y0 = funpack2(accY[i][0]), y1 = funpack2(accY[i][1]);
            float2 z0 = funpack2(accZ[i][0]), z1 = funpack2(accZ[i][1]);
            *(float4*)&Y[node * NP + og * 4] = make_float4(y0.x, y0.y, y1.x, y1.y);
            *(float4*)&Z[node * NP + og * 4] =
                make_float4(z0.x + b4[0], z0.y + b4[1], z1.x + b4[2], z1.y + b4[3]);
        }
    }
}

// ---------------- CSR gather: H = [relu](mean_{src in N(n)} Y[src] [+ Z[n]]) --
template <int NP4, int RELU, int HAS_Z>
__global__ void gather_kernel(const float* __restrict__ Y,
                              const float* __restrict__ Z,
                              float* __restrict__ H) {
    int idx = blockIdx.x * blockDim.x + threadIdx.x;
    if (idx >= N_NODES * NP4) return;
    int n = idx / NP4;
    int f = idx - n * NP4;
    constexpr int np = NP4 * 4;
    int s = g_row[n], e = g_row[n + 1];
    float ax = 0.f, ay = 0.f, az = 0.f, aw = 0.f;
    int i = s;
    for (; i + 3 < e; i += 4) {                 // 4-way MLP on the edge loop
        int s0 = g_csr[i], s1 = g_csr[i + 1], s2 = g_csr[i + 2], s3 = g_csr[i + 3];
        float4 v0 = *(const float4*)&Y[s0 * np + f * 4];
        float4 v1 = *(const float4*)&Y[s1 * np + f * 4];
        float4 v2 = *(const float4*)&Y[s2 * np + f * 4];
        float4 v3 = *(const float4*)&Y[s3 * np + f * 4];
        ax += (v0.x + v1.x) + (v2.x + v3.x);
        ay += (v0.y + v1.y) + (v2.y + v3.y);
        az += (v0.z + v1.z) + (v2.z + v3.z);
        aw += (v0.w + v1.w) + (v2.w + v3.w);
    }
    for (; i < e; i++) {
        int s0 = g_csr[i];
        float4 v0 = *(const float4*)&Y[s0 * np + f * 4];
        ax += v0.x; ay += v0.y; az += v0.z; aw += v0.w;
    }
    int deg = e - s;
    float inv = 1.f / (float)(deg > 1 ? deg : 1);
    ax *= inv; ay *= inv; az *= inv; aw *= inv;
    if (HAS_Z) {
        float4 z = *(const float4*)&Z[n * np + f * 4];
        ax += z.x; ay += z.y; az += z.z; aw += z.w;
    }
    if (RELU) {
        ax = fmaxf(ax, 0.f); ay = fmaxf(ay, 0.f);
        az = fmaxf(az, 0.f); aw = fmaxf(aw, 0.f);
    }
    *(float4*)&H[n * np + f * 4] = make_float4(ax, ay, az, aw);
}

// ---------------- final layer: mu = A@Wlm + H2@Wrm + bm ; lv analogous ------
// Weights transposed in smem -> both f32x2 operands are direct 64-bit loads.
__global__ void final_kernel(const float* __restrict__ A,
                             const float* __restrict__ H2,
                             const float* __restrict__ Wlm,
                             const float* __restrict__ Wrm,
                             const float* __restrict__ bm,
                             const float* __restrict__ Wll,
                             const float* __restrict__ Wrl,
                             const float* __restrict__ bl,
                             float* __restrict__ out, int half) {
    __shared__ __align__(8) float s_wlm[OUT_DIM * H2_DIM];  // [j][k]
    __shared__ __align__(8) float s_wrm[OUT_DIM * H2_DIM];
    __shared__ __align__(8) float s_wll[OUT_DIM * H2_DIM];
    __shared__ __align__(8) float s_wrl[OUT_DIM * H2_DIM];
    __shared__ float s_b[2 * OUT_DIM];
    int tid = threadIdx.x;
    for (int i = tid; i < H2_DIM * OUT_DIM; i += blockDim.x) {
        int k = i / OUT_DIM, j = i - k * OUT_DIM;
        s_wlm[j * H2_DIM + k] = Wlm[i]; s_wrm[j * H2_DIM + k] = Wrm[i];
        s_wll[j * H2_DIM + k] = Wll[i]; s_wrl[j * H2_DIM + k] = Wrl[i];
    }
    if (tid < 2 * OUT_DIM) s_b[tid] = (tid < OUT_DIM) ? bm[tid] : bl[tid - OUT_DIM];
    __syncthreads();

    int idx = blockIdx.x * blockDim.x + tid;
    if (idx >= N_NODES * 2 * OUT_DIM) return;
    int n = idx / (2 * OUT_DIM);
    int j = idx - n * (2 * OUT_DIM);
    const float* wl = (j < OUT_DIM) ? s_wlm : s_wll;
    const float* wr = (j < OUT_DIM) ? s_wrm : s_wrl;
    int jj = (j < OUT_DIM) ? j : j - OUT_DIM;
    const float* a = A + n * NP2;
    const float* h = H2 + n * NP2;
    const float* wlr = wl + jj * H2_DIM;
    const float* wrr = wr + jj * H2_DIM;
    ull accA = 0ULL, accB = 0ULL;
#pragma unroll
    for (int kp = 0; kp < H2_DIM / 2; kp++) {
        ffma2(accA, *(const ull*)(a + 2 * kp), *(const ull*)(wlr + 2 * kp));
        ffma2(accB, *(const ull*)(h + 2 * kp), *(const ull*)(wrr + 2 * kp));
    }
    float2 ra = funpack2(accA), rb = funpack2(accB);
    float acc = s_b[j] + (ra.x + ra.y) + (rb.x + rb.y);
    out[(j < OUT_DIM ? 0 : half) + n * OUT_DIM + jj] = acc;
}

// ---------------- launch ----------------
extern "C" void kernel_launch(void* const* d_in, const int* in_sizes, int n_in,
                              void* d_out, int out_size) {
    const float* x    = (const float*)d_in[0];
    const void*  ei   = d_in[1];
    const float* Wl1  = (const float*)d_in[2];
    const float* Wr1  = (const float*)d_in[3];
    const float* b1   = (const float*)d_in[4];
    const float* Wl2  = (const float*)d_in[5];
    const float* Wr2  = (const float*)d_in[6];
    const float* b2   = (const float*)d_in[7];
    const float* Wlmu = (const float*)d_in[8];
    const float* Wrmu = (const float*)d_in[9];
    const float* bmu  = (const float*)d_in[10];
    const float* Wllv = (const float*)d_in[11];
    const float* Wrlv = (const float*)d_in[12];
    const float* blv  = (const float*)d_in[13];
    float* out = (float*)d_out;

    float *A, *B, *C;
    cudaGetSymbolAddress((void**)&A, g_bufA);
    cudaGetSymbolAddress((void**)&B, g_bufB);
    cudaGetSymbolAddress((void**)&C, g_bufC);

    // One-time side-stream/event creation (host resources only; no device mem).
    static cudaStream_t s_csr = nullptr;
    static cudaEvent_t  s_fork = nullptr, s_join = nullptr;
    if (!s_csr) {
        cudaStreamCreateWithFlags(&s_csr, cudaStreamNonBlocking);
        cudaEventCreateWithFlags(&s_fork, cudaEventDisableTiming);
        cudaEventCreateWithFlags(&s_join, cudaEventDisableTiming);
    }

    // Fork: CSR build runs on the side branch, concurrent with gemm1.
    cudaEventRecord(s_fork, 0);
    cudaStreamWaitEvent(s_csr, s_fork, 0);

    init_kernel<<<SCAN_NBLK, SCAN_BLK, 0, s_csr>>>(ei);               // #0
    hist_kernel<<<(N_EDGES / 2 + 511) / 512, 512, 0, s_csr>>>(ei);    // #1
    scan1_kernel<<<SCAN_NBLK, SCAN_BLK, 0, s_csr>>>();                // #2
    scan2_kernel<<<1, 64, 0, s_csr>>>();                              // #3
    scan3_kernel<<<SCAN_NBLK, SCAN_BLK, 0, s_csr>>>();                // #4

    // Layer 1 transform (128 -> 117) on the main branch; launch index 5
    // so ncu -s 5 profiles it next round.
    gemm_dual_kernel<NP1><<<(N_NODES + 63) / 64, (NP1 / 4) * 16>>>(
        x, IN_DIM, IN_DIM, H1_DIM, Wl1, Wr1, b1, A, B);               // #5

    fill_kernel<<<(N_EDGES / 2 + 511) / 512, 512, 0, s_csr>>>(ei);    // #6
    cudaEventRecord(s_join, s_csr);
    cudaStreamWaitEvent(0, s_join, 0);                                // join

    // Layer 1 aggregate (117-dim)
    gather_kernel<NP1 / 4, 1, 1><<<(N_NODES * (NP1 / 4) + 255) / 256, 256>>>(
        A, B, C);                                                     // C=h1

    // Layer 2: transform first (117 -> 42), then aggregate 42-dim
    gemm_dual_kernel<NP2><<<(N_NODES + 63) / 64, (NP2 / 4) * 16>>>(
        C, NP1, H1_DIM, H2_DIM, Wl2, Wr2, b2, A, B);
    gather_kernel<NP2 / 4, 1, 1><<<(N_NODES * (NP2 / 4) + 255) / 256, 256>>>(
        A, B, C);                                                     // C=h2

    // Layer 3: aggregate h2 once (shared by mu and logvar), then tiny GEMM
    gather_kernel<NP2 / 4, 0, 0><<<(N_NODES * (NP2 / 4) + 255) / 256, 256>>>(
        C, nullptr, A);
    final_kernel<<<(N_NODES * 2 * OUT_DIM + 255) / 256, 256>>>(
        A, C, Wlmu, Wrmu, bmu, Wllv, Wrlv, blv, out, out_size / 2);
}